// round 7
// baseline (speedup 1.0000x reference)
#include <cuda_runtime.h>
#include <math.h>

#define BLK 256

// Precomputed circular-conv spectral kernels (weight-only, once per launch):
//   g[c][kh][d] = fold(kh) * sum_kw W[kw][kh][c] * e^{+i 2 pi kw d / H}
// fold = 1/H^2 at boundary bins (kh=0, Nyquist), 2/H^2 interior (folds ortho
// norm + C2R interior doubling).  Complex row stride RS = 2H+2 (8B aligned).
#define GX_SZ (72 * 34)
#define GZ_SZ (40 * 18)
__device__ float g_glob[GX_SZ + GZ_SZ];

template <int H>
__device__ __forceinline__ void fill_g(const float *__restrict__ cw,
                                       float *__restrict__ g,
                                       int tid, int nth) {
  constexpr int KH = H / 2 + 1;
  constexpr int RS = 2 * H + 2;
  const float sc = 1.f / (float)(H * H);
  for (int i = tid; i < 8 * KH * H; i += nth) {
    int d = i % H;
    int kh = (i / H) % KH;
    int c = i / (H * KH);
    float fold = (kh == 0 || kh == KH - 1) ? sc : 2.f * sc;
    float gr = 0.f, gi = 0.f;
    for (int kw = 0; kw < H; ++kw) {
      float wr = cw[((kw * KH + kh) * 8 + c) * 2];
      float wi = cw[((kw * KH + kh) * 8 + c) * 2 + 1];
      float s, co;
      sincosf(6.283185307179586f * (float)((kw * d) & (H - 1)) / (float)H, &s, &co);
      gr += wr * co - wi * s;
      gi += wr * s + wi * co;
    }
    g[(c * KH + kh) * RS + 2 * d] = gr * fold;
    g[(c * KH + kh) * RS + 2 * d + 1] = gi * fold;
  }
}

__global__ void g_kernel(const float *__restrict__ cw,
                         const float *__restrict__ cwz) {
  fill_g<16>(cw, g_glob, threadIdx.x, blockDim.x);
  fill_g<8>(cwz, g_glob + GX_SZ, threadIdx.x, blockDim.x);
}

struct BranchP {
  const float *nog, *nob, *cvw, *cvb, *w1, *b1, *w2, *b2;
  int tok_off, goff;
};

#define POOL_FLOATS 10704  // x: 2304+2448+2304+2448+1200; z: 9664

// ---------------------------------------------------------------------------
// One branch for NB batch elements.  H in {16,8}, N=H*H, C=8, n = h*H + w.
// Spectral: rfft over h (KH bins), circular conv over w with g, C2R over h.
// Bank audit (per instruction across the warp): pass A data reads 9w%32
// distinct / tw broadcast; pass BC A/g reads 4 distinct rows x 8-lane
// broadcast; pass D Vb reads 18w%32 distinct pairs; all writes distinct.
// ---------------------------------------------------------------------------
template <int H, int NB>
__device__ __forceinline__ void run_branch(
    const float *__restrict__ x, float *__restrict__ out, int bid,
    const float *__restrict__ n1g, const float *__restrict__ n1b,
    const float *__restrict__ n2g, const float *__restrict__ n2b,
    const BranchP &P, float *pool)
{
  constexpr int N = H * H;
  constexpr int KH = H / 2 + 1;
  constexpr int RS = 2 * H + 2;       // complex row stride (floats)
  constexpr int S1S = N * 9;          // padded LN1 rows per sub-batch
  constexpr int ASZ = 8 * KH * RS;    // bufA floats per sub-batch
  constexpr int VSZ = 8 * H * KH * 2; // bufV floats per sub-batch
  constexpr int GSZ = 8 * KH * RS;

  float *s1 = pool;                // NB*S1S : LN1 output [n][9]
  float *bufA = s1 + NB * S1S;     // NB*ASZ : pass A out; later s2
  float *bufV = bufA + NB * ASZ;   // NB*VSZ : conv out, [c][w][kh] complex
  float *sgk = bufV + NB * VSZ;    // GSZ    : spectral conv kernel
  float *wsm = sgk + GSZ;          // 1200   : small weights + twiddles

  const int tid = threadIdx.x;
  const int b0 = bid * NB;

  float *scw = wsm;                         // 576 conv w [o][i][k]
  float *scb = wsm + 576;                   // 8
  float *sw1 = wsm + 584;                   // 256 mlp w1 [c][j]
  float *sb1 = wsm + 840;                   // 32
  float *sw2 = wsm + 872;                   // 256 mlp w2 [j][o]
  float *sb2 = wsm + 1128;                  // 8
  float *sn2g = wsm + 1136;                 // 8
  float *sn2b = wsm + 1144;                 // 8
  float *snog = wsm + 1152;                 // 8
  float *snob = wsm + 1160;                 // 8
  float2 *tw = (float2 *)(wsm + 1168);      // 16 x (cos, sin)

  for (int i = tid; i < 576; i += BLK) scw[i] = P.cvw[i];
  for (int i = tid; i < 256; i += BLK) { sw1[i] = P.w1[i]; sw2[i] = P.w2[i]; }
  for (int i = tid; i < GSZ; i += BLK) sgk[i] = g_glob[P.goff + i];
  if (tid < 32) sb1[tid] = P.b1[tid];
  if (tid < 8) {
    scb[tid] = P.cvb[tid];
    sb2[tid] = P.b2[tid];
    sn2g[tid] = n2g[tid];
    sn2b[tid] = n2b[tid];
    snog[tid] = P.nog[tid];
    snob[tid] = P.nob[tid];
  }
  if (tid < H) {
    float s, c;
    sincosf(6.283185307179586f * (float)tid / (float)H, &s, &c);
    tw[tid] = make_float2(c, s);
  }

  // ---- LN1 ----
  for (int idx = tid; idx < NB * N; idx += BLK) {
    int sub = idx / N, n = idx % N;
    const float *gp = x + ((size_t)(b0 + sub) * 320 + P.tok_off + n) * 8;
    float4 p0 = *(const float4 *)gp;
    float4 p1 = *(const float4 *)(gp + 4);
    float v[8] = {p0.x, p0.y, p0.z, p0.w, p1.x, p1.y, p1.z, p1.w};
    float m = 0.f;
#pragma unroll
    for (int c = 0; c < 8; ++c) m += v[c];
    m *= 0.125f;
    float var = 0.f;
#pragma unroll
    for (int c = 0; c < 8; ++c) { float d = v[c] - m; var += d * d; }
    var *= 0.125f;
    float rs = rsqrtf(var + 1e-5f);
    float *row = s1 + sub * S1S + n * 9;
#pragma unroll
    for (int c = 0; c < 8; ++c)
      row[c] = (v[c] - m) * rs * __ldg(n1g + c) + __ldg(n1b + c);
  }
  __syncthreads();

  // ---- Pass A: rfft over h, column-cached.  Item = (sub,c,w,khP);
  // loads H values once, emits bins kh = 2k+khP (fixed trip count + one
  // predicated odd bin since KH is odd).
  for (int idx = tid; idx < NB * 8 * H * 2; idx += BLK) {
    int khP = idx & 1;
    int w = (idx >> 1) % H;
    int rc = idx / (2 * H);
    int c = rc % 8, sub = rc / 8;
    const float *sp = s1 + sub * S1S;
    float v[H];
#pragma unroll
    for (int h = 0; h < H; ++h) v[h] = sp[(h * H + w) * 9 + c];
    float2 *Ab = (float2 *)(bufA + sub * ASZ);
#pragma unroll
    for (int k = 0; k < KH / 2; ++k) {
      int kh = 2 * k + khP;
      float ar = 0.f, ai = 0.f;
#pragma unroll
      for (int h = 0; h < H; ++h) {
        float2 t = tw[(h * kh) & (H - 1)];
        ar += v[h] * t.x;
        ai -= v[h] * t.y;
      }
      Ab[(c * KH + kh) * (RS / 2) + w] = make_float2(ar, ai);
    }
    if (khP == 0) {  // KH odd: bin kh = KH-1 (Nyquist) for even-parity items
      constexpr int kh = KH - 1;
      float ar = 0.f;
#pragma unroll
      for (int h = 0; h < H; ++h) ar += (h & 1) ? -v[h] : v[h];
      Ab[(c * KH + kh) * (RS / 2) + w] = make_float2(ar, 0.f);
    }
  }
  __syncthreads();

  // ---- Pass BC: circular conv over w with g; paired outputs share the
  // rolling A value and the g taps.  Item = (sub,c,kh,wq), outputs 2wq,2wq+1.
  for (int idx = tid; idx < NB * 8 * KH * (H / 2); idx += BLK) {
    int wq = idx % (H / 2);
    int kh = (idx / (H / 2)) % KH;
    int rc = idx / ((H / 2) * KH);
    int c = rc % 8, sub = rc / 8;
    const float2 *Ab = (const float2 *)(bufA + sub * ASZ) + (c * KH + kh) * (RS / 2);
    const float2 *gb = (const float2 *)(sgk) + (c * KH + kh) * (RS / 2);
    int wp = 2 * wq;
    float o0r = 0.f, o0i = 0.f, o1r = 0.f, o1i = 0.f;
    float2 v0 = Ab[(wp + 1) & (H - 1)];
    float2 vd = v0, gp;
#pragma unroll
    for (int d = 0; d < H; ++d) {
      float2 gd = gb[d];
      o1r += vd.x * gd.x - vd.y * gd.y;   // out1 lag d: A[wp+1-d]*g[d]
      o1i += vd.x * gd.y + vd.y * gd.x;
      if (d > 0) {
        o0r += vd.x * gp.x - vd.y * gp.y; // out0 lag d-1: A[wp-(d-1)]*g[d-1]
        o0i += vd.x * gp.y + vd.y * gp.x;
      }
      gp = gd;
      if (d < H - 1) vd = Ab[(wp - d) & (H - 1)];
    }
    o0r += v0.x * gp.x - v0.y * gp.y;     // cyclic closing term d = H-1
    o0i += v0.x * gp.y + v0.y * gp.x;
    float2 *Vb = (float2 *)(bufV + sub * VSZ);
    Vb[(c * H + wp) * KH + kh] = make_float2(o0r, o0i);
    Vb[(c * H + wp + 1) * KH + kh] = make_float2(o1r, o1i);
  }
  __syncthreads();

  // ---- Pass D: C2R over h, column-cached.  Item = (sub,c,w,hP); caches KH
  // bins in registers, emits h = 2k+hP into s2 (aliases bufA).  Doubling of
  // interior bins folded into g, so each term is one cmul-real.
  for (int idx = tid; idx < NB * 8 * H * 2; idx += BLK) {
    int hP = idx & 1;
    int w = (idx >> 1) % H;
    int rc = idx / (2 * H);
    int c = rc % 8, sub = rc / 8;
    const float2 *Vb = (const float2 *)(bufV + sub * VSZ) + (c * H + w) * KH;
    float2 Cv[KH];
#pragma unroll
    for (int kh = 0; kh < KH; ++kh) Cv[kh] = Vb[kh];
    float base = Cv[0].x + (hP ? -Cv[KH - 1].x : Cv[KH - 1].x);
    float *s2 = bufA + sub * ASZ;
#pragma unroll
    for (int k = 0; k < H / 2; ++k) {
      int h = 2 * k + hP;
      float v = base;
#pragma unroll
      for (int kh = 1; kh < KH - 1; ++kh) {
        float2 t = tw[(h * kh) & (H - 1)];
        v += Cv[kh].x * t.x - Cv[kh].y * t.y;
      }
      s2[(h * H + w) * 9 + c] = v;
    }
  }
  __syncthreads();

  // ---- tail: LN2 -> MLP -> conv3x3(s1)+mlp -> LN -> relu -> store ----
  for (int idx = tid; idx < NB * N; idx += BLK) {
    int sub = idx / N, n = idx % N;
    const float *s2 = bufA + sub * ASZ;
    const float *sp = s1 + sub * S1S;

    float v[8];
#pragma unroll
    for (int c = 0; c < 8; ++c) v[c] = s2[n * 9 + c];
    float m = 0.f;
#pragma unroll
    for (int c = 0; c < 8; ++c) m += v[c];
    m *= 0.125f;
    float var = 0.f;
#pragma unroll
    for (int c = 0; c < 8; ++c) { float d = v[c] - m; var += d * d; }
    var *= 0.125f;
    float rs = rsqrtf(var + 1e-5f);
#pragma unroll
    for (int c = 0; c < 8; ++c) v[c] = (v[c] - m) * rs * sn2g[c] + sn2b[c];

    float y[8];
#pragma unroll
    for (int o = 0; o < 8; ++o) y[o] = sb2[o];
#pragma unroll 4
    for (int j = 0; j < 32; ++j) {
      float hj = sb1[j];
#pragma unroll
      for (int c = 0; c < 8; ++c) hj += v[c] * sw1[c * 32 + j];
      float g = 0.5f * hj * (1.f + erff(hj * 0.70710678118654752f));
#pragma unroll
      for (int o = 0; o < 8; ++o) y[o] += g * sw2[j * 8 + o];
    }

    int h = n / H, w = n % H;
    float acc[8];
#pragma unroll
    for (int o = 0; o < 8; ++o) acc[o] = scb[o] + y[o];
#pragma unroll
    for (int dh = -1; dh <= 1; ++dh) {
      int hh = h + dh;
      if (hh < 0 || hh >= H) continue;
#pragma unroll
      for (int dw = -1; dw <= 1; ++dw) {
        int ww = w + dw;
        if (ww < 0 || ww >= H) continue;
        const float *row = sp + (hh * H + ww) * 9;
        int k = (dh + 1) * 3 + (dw + 1);
#pragma unroll
        for (int i = 0; i < 8; ++i) {
          float xv = row[i];
#pragma unroll
          for (int o = 0; o < 8; ++o)
            acc[o] += xv * scw[(o * 8 + i) * 9 + k];
        }
      }
    }

    float mo = 0.f;
#pragma unroll
    for (int o = 0; o < 8; ++o) mo += acc[o];
    mo *= 0.125f;
    float vo = 0.f;
#pragma unroll
    for (int o = 0; o < 8; ++o) { float d = acc[o] - mo; vo += d * d; }
    vo *= 0.125f;
    float rso = rsqrtf(vo + 1e-5f);
    float rr[8];
#pragma unroll
    for (int o = 0; o < 8; ++o)
      rr[o] = fmaxf((acc[o] - mo) * rso * snog[o] + snob[o], 0.f);

    float *gp = out + ((size_t)(b0 + sub) * 320 + P.tok_off + n) * 8;
    *(float4 *)gp = make_float4(rr[0], rr[1], rr[2], rr[3]);
    *(float4 *)(gp + 4) = make_float4(rr[4], rr[5], rr[6], rr[7]);
  }
}

// Both branches in one launch: blocks [0,Bx) -> H=16 x-branch,
// [Bx, Bx+gz) -> H=8 z-branch (4 batches per block).
__global__ void __launch_bounds__(BLK) sg_fused(
    const float *__restrict__ x, float *__restrict__ out, int Bx,
    const float *__restrict__ n1g, const float *__restrict__ n1b,
    const float *__restrict__ n2g, const float *__restrict__ n2b,
    BranchP Px, BranchP Pz)
{
  __shared__ __align__(16) float pool[POOL_FLOATS];
  int bid = blockIdx.x;
  if (bid < Bx)
    run_branch<16, 1>(x, out, bid, n1g, n1b, n2g, n2b, Px, pool);
  else
    run_branch<8, 4>(x, out, bid - Bx, n1g, n1b, n2g, n2b, Pz, pool);
}

extern "C" void kernel_launch(void *const *d_in, const int *in_sizes, int n_in,
                              void *d_out, int out_size) {
  const float *x = (const float *)d_in[0];
  const float *n1g = (const float *)d_in[1], *n1b = (const float *)d_in[2];
  const float *n2g = (const float *)d_in[3], *n2b = (const float *)d_in[4];
  const float *n3g = (const float *)d_in[5], *n3b = (const float *)d_in[6];
  const float *n4g = (const float *)d_in[7], *n4b = (const float *)d_in[8];
  const float *c1w = (const float *)d_in[9], *c1b = (const float *)d_in[10];
  const float *c2w = (const float *)d_in[11], *c2b = (const float *)d_in[12];
  const float *m1w1 = (const float *)d_in[13], *m1b1 = (const float *)d_in[14];
  const float *m1w2 = (const float *)d_in[15], *m1b2 = (const float *)d_in[16];
  const float *m2w1 = (const float *)d_in[17], *m2b1 = (const float *)d_in[18];
  const float *m2w2 = (const float *)d_in[19], *m2b2 = (const float *)d_in[20];
  const float *cw = (const float *)d_in[21], *cwz = (const float *)d_in[22];
  float *out = (float *)d_out;
  int B = in_sizes[0] / (320 * 8);

  // weight-only spectral kernel precompute (cheap, once per launch)
  g_kernel<<<1, BLK>>>(cw, cwz);

  BranchP Px = {n3g, n3b, c1w, c1b, m1w1, m1b1, m1w2, m1b2, 64, 0};
  BranchP Pz = {n4g, n4b, c2w, c2b, m2w1, m2b1, m2w2, m2b2, 0, GX_SZ};

  int gz = (B + 3) / 4;
  sg_fused<<<B + gz, BLK>>>(x, out, B, n1g, n1b, n2g, n2b, Px, Pz);
}

// round 16
// speedup vs baseline: 1.0583x; 1.0583x over previous
#include <cuda_runtime.h>
#include <math.h>

#define BLK 256

// ---------------------------------------------------------------------------
// Compile-time twiddle tables: index p -> cos/sin(2*pi*p/16).  __device__
// constexpr so device code can reference them WITHOUT --expt-relaxed-constexpr
// (the GB300 harness nvcc does not pass that flag).  All indices are
// compile-time after parity-template unroll => folded to FFMA immediates.
// ---------------------------------------------------------------------------
__device__ constexpr float TC16[16] = {
    1.f, 0.92387953251128674f, 0.70710678118654752f, 0.38268343236508977f,
    0.f, -0.38268343236508977f, -0.70710678118654752f, -0.92387953251128674f,
    -1.f, -0.92387953251128674f, -0.70710678118654752f, -0.38268343236508977f,
    0.f, 0.38268343236508977f, 0.70710678118654752f, 0.92387953251128674f};
__device__ constexpr float TS16[16] = {
    0.f, 0.38268343236508977f, 0.70710678118654752f, 0.92387953251128674f,
    1.f, 0.92387953251128674f, 0.70710678118654752f, 0.38268343236508977f,
    0.f, -0.38268343236508977f, -0.70710678118654752f, -0.92387953251128674f,
    -1.f, -0.92387953251128674f, -0.70710678118654752f, -0.38268343236508977f};

// Precomputed circular-conv spectral kernels (weight-only, once per launch):
//   g[c][kh][d] = fold(kh) * sum_kw W[kw][kh][c] * e^{+i 2 pi kw d / H}
// fold = 1/H^2 at boundary bins (kh=0, Nyquist), 2/H^2 interior.
#define GX_SZ (72 * 34)
#define GZ_SZ (40 * 18)
__device__ float g_glob[GX_SZ + GZ_SZ];

// Constant-memory parameter block: all small weights, one block per branch.
// Reads go through the constant port (LDC/LDCU) instead of the smem crossbar.
#define CPB 1184
#define CPN (2 * CPB)
__constant__ float CP[CPN];
__device__ float g_stage[CPN];

#define O_SCW 0     // 576 conv w [o][i][k]
#define O_SCB 576   // 8
#define O_W1 584    // 256 mlp w1 [c][j]
#define O_B1 840    // 32
#define O_W2 872    // 256 mlp w2 [j][o]
#define O_B2 1128   // 8
#define O_N2G 1136  // 8
#define O_N2B 1144  // 8
#define O_NOG 1152  // 8
#define O_NOB 1160  // 8
#define O_N1G 1168  // 8
#define O_N1B 1176  // 8

template <int H>
__device__ __forceinline__ void fill_g(const float *__restrict__ cw,
                                       float *__restrict__ g,
                                       int tid, int nth) {
  constexpr int KH = H / 2 + 1;
  constexpr int RS = 2 * H + 2;
  const float sc = 1.f / (float)(H * H);
  for (int i = tid; i < 8 * KH * H; i += nth) {
    int d = i % H;
    int kh = (i / H) % KH;
    int c = i / (H * KH);
    float fold = (kh == 0 || kh == KH - 1) ? sc : 2.f * sc;
    float gr = 0.f, gi = 0.f;
    for (int kw = 0; kw < H; ++kw) {
      float wr = cw[((kw * KH + kh) * 8 + c) * 2];
      float wi = cw[((kw * KH + kh) * 8 + c) * 2 + 1];
      float s, co;
      sincosf(6.283185307179586f * (float)((kw * d) & (H - 1)) / (float)H, &s, &co);
      gr += wr * co - wi * s;
      gi += wr * s + wi * co;
    }
    g[(c * KH + kh) * RS + 2 * d] = gr * fold;
    g[(c * KH + kh) * RS + 2 * d + 1] = gi * fold;
  }
}

// Prep: pack all small weights into g_stage (then memcpy'd to CP) and build g.
__global__ void prep_kernel(
    const float *n1g, const float *n1b, const float *n2g, const float *n2b,
    const float *n3g, const float *n3b, const float *n4g, const float *n4b,
    const float *c1w, const float *c1b, const float *c2w, const float *c2b,
    const float *m1w1, const float *m1b1, const float *m1w2, const float *m1b2,
    const float *m2w1, const float *m2b1, const float *m2w2, const float *m2b2,
    const float *cw, const float *cwz) {
  int t = threadIdx.x;
  for (int i = t; i < 576; i += BLK) {
    g_stage[O_SCW + i] = c1w[i];
    g_stage[CPB + O_SCW + i] = c2w[i];
  }
  for (int i = t; i < 256; i += BLK) {
    g_stage[O_W1 + i] = m1w1[i];
    g_stage[O_W2 + i] = m1w2[i];
    g_stage[CPB + O_W1 + i] = m2w1[i];
    g_stage[CPB + O_W2 + i] = m2w2[i];
  }
  if (t < 32) {
    g_stage[O_B1 + t] = m1b1[t];
    g_stage[CPB + O_B1 + t] = m2b1[t];
  }
  if (t < 8) {
    g_stage[O_SCB + t] = c1b[t];
    g_stage[O_B2 + t] = m1b2[t];
    g_stage[O_N2G + t] = n2g[t];
    g_stage[O_N2B + t] = n2b[t];
    g_stage[O_NOG + t] = n3g[t];
    g_stage[O_NOB + t] = n3b[t];
    g_stage[O_N1G + t] = n1g[t];
    g_stage[O_N1B + t] = n1b[t];
    g_stage[CPB + O_SCB + t] = c2b[t];
    g_stage[CPB + O_B2 + t] = m2b2[t];
    g_stage[CPB + O_N2G + t] = n2g[t];
    g_stage[CPB + O_N2B + t] = n2b[t];
    g_stage[CPB + O_NOG + t] = n4g[t];
    g_stage[CPB + O_NOB + t] = n4b[t];
    g_stage[CPB + O_N1G + t] = n1g[t];
    g_stage[CPB + O_N1B + t] = n1b[t];
  }
  fill_g<16>(cw, g_glob, t, BLK);
  fill_g<8>(cwz, g_glob + GX_SZ, t, BLK);
}

// rfft bins over h with compile-time twiddles (khP = bin parity).
template <int H, int khP>
__device__ __forceinline__ void passA_bins(const float *v, float2 *dst, int w) {
  constexpr int KH = H / 2 + 1;
  constexpr int RS2 = H + 1;
  constexpr int ST = 16 / H;
#pragma unroll
  for (int kh = khP; kh < KH; kh += 2) {
    float ar = 0.f, ai = 0.f;
#pragma unroll
    for (int h = 0; h < H; ++h) {
      const int p = (h * kh * ST) & 15;
      ar += v[h] * TC16[p];
      ai -= v[h] * TS16[p];
    }
    dst[kh * RS2 + w] = make_float2(ar, ai);
  }
}

// C2R over h with compile-time twiddles (hP = output parity).
template <int H, int hP, int CS>
__device__ __forceinline__ void passD_rows(const float2 *Cv, float *s2c, int w) {
  constexpr int KH = H / 2 + 1;
  constexpr int ST = 16 / H;
  float base = Cv[0].x + (hP ? -Cv[KH - 1].x : Cv[KH - 1].x);
#pragma unroll
  for (int k = 0; k < H / 2; ++k) {
    const int h = 2 * k + hP;
    float val = base;
#pragma unroll
    for (int kh = 1; kh < KH - 1; ++kh) {
      const int p = (h * kh * ST) & 15;
      val += Cv[kh].x * TC16[p] - Cv[kh].y * TS16[p];
    }
    s2c[h * H + w] = val;
  }
}

#define POOL_FLOATS 9280  // x: 2080+2448+2304+2448; z: 2304+2880+2560+720

// ---------------------------------------------------------------------------
// One branch for NB batch elements.  H in {16,8}, N=H*H, C=8, n = h*H + w.
// s1/s2 are channel-major [c][n] (stride CS) -> all scalar smem accesses
// conflict-free.  Small weights come from constant memory (CP, offset Q).
// ---------------------------------------------------------------------------
template <int H, int NB>
__device__ __forceinline__ void run_branch(
    const float *__restrict__ x, float *__restrict__ out, int bid,
    int tok_off, int goff, int Q, float *pool)
{
  constexpr int N = H * H;
  constexpr int KH = H / 2 + 1;
  constexpr int RS = 2 * H + 2;       // complex row stride (floats)
  constexpr int CS = N + (H == 8 ? 8 : 4);  // channel stride (bank-staggered)
  constexpr int ASZ = 8 * KH * RS;    // bufA floats per sub (>= 8*CS for s2)
  constexpr int VSZ = 8 * H * KH * 2;
  constexpr int GSZ = 8 * KH * RS;
  static_assert(ASZ >= 8 * CS, "s2 overlay");

  float *s1 = pool;              // NB*8*CS : LN1 out, channel-major
  float *bufA = s1 + NB * 8 * CS;  // NB*ASZ : pass A out; later s2
  float *bufV = bufA + NB * ASZ;   // NB*VSZ : conv out, [c][w][kh] complex
  float *sgk = bufV + NB * VSZ;    // GSZ    : spectral conv kernel g

  const int tid = threadIdx.x;
  const int b0 = bid * NB;

  for (int i = tid; i < GSZ; i += BLK) sgk[i] = g_glob[goff + i];

  // ---- LN1 -> s1 channel-major ----
  for (int idx = tid; idx < NB * N; idx += BLK) {
    int sub = idx / N, n = idx % N;
    const float *gp = x + ((size_t)(b0 + sub) * 320 + tok_off + n) * 8;
    float4 p0 = *(const float4 *)gp;
    float4 p1 = *(const float4 *)(gp + 4);
    float v[8] = {p0.x, p0.y, p0.z, p0.w, p1.x, p1.y, p1.z, p1.w};
    float m = 0.f;
#pragma unroll
    for (int c = 0; c < 8; ++c) m += v[c];
    m *= 0.125f;
    float var = 0.f;
#pragma unroll
    for (int c = 0; c < 8; ++c) { float d = v[c] - m; var += d * d; }
    var *= 0.125f;
    float rs = rsqrtf(var + 1e-5f);
    float *sc = s1 + sub * 8 * CS;
#pragma unroll
    for (int c = 0; c < 8; ++c)
      sc[c * CS + n] = (v[c] - m) * rs * CP[Q + O_N1G + c] + CP[Q + O_N1B + c];
  }
  __syncthreads();

  // ---- Pass A: rfft over h (twiddles = immediates) ----
  for (int idx = tid; idx < NB * 8 * H * 2; idx += BLK) {
    int khP = idx & 1;
    int w = (idx >> 1) % H;
    int rc = idx / (2 * H);
    int c = rc % 8, sub = rc / 8;
    const float *sp = s1 + sub * 8 * CS + c * CS;
    float v[H];
#pragma unroll
    for (int h = 0; h < H; ++h) v[h] = sp[h * H + w];
    float2 *dst = (float2 *)(bufA + sub * ASZ) + c * KH * (RS / 2);
    if (khP == 0) passA_bins<H, 0>(v, dst, w);
    else          passA_bins<H, 1>(v, dst, w);
  }
  __syncthreads();

  // ---- Pass BC: circular conv over w with g; paired outputs share the
  // rolling A value and the g taps.  Item = (sub,c,kh,wq), outputs 2wq,2wq+1.
  for (int idx = tid; idx < NB * 8 * KH * (H / 2); idx += BLK) {
    int wq = idx % (H / 2);
    int kh = (idx / (H / 2)) % KH;
    int rc = idx / ((H / 2) * KH);
    int c = rc % 8, sub = rc / 8;
    const float2 *Ab = (const float2 *)(bufA + sub * ASZ) + (c * KH + kh) * (RS / 2);
    const float2 *gb = (const float2 *)(sgk) + (c * KH + kh) * (RS / 2);
    int wp = 2 * wq;
    float o0r = 0.f, o0i = 0.f, o1r = 0.f, o1i = 0.f;
    float2 v0 = Ab[(wp + 1) & (H - 1)];
    float2 vd = v0, gp;
#pragma unroll
    for (int d = 0; d < H; ++d) {
      float2 gd = gb[d];
      o1r += vd.x * gd.x - vd.y * gd.y;   // out1 lag d: A[wp+1-d]*g[d]
      o1i += vd.x * gd.y + vd.y * gd.x;
      if (d > 0) {
        o0r += vd.x * gp.x - vd.y * gp.y; // out0 lag d-1: A[wp-(d-1)]*g[d-1]
        o0i += vd.x * gp.y + vd.y * gp.x;
      }
      gp = gd;
      if (d < H - 1) vd = Ab[(wp - d) & (H - 1)];
    }
    o0r += v0.x * gp.x - v0.y * gp.y;     // cyclic closing term d = H-1
    o0i += v0.x * gp.y + v0.y * gp.x;
    float2 *Vb = (float2 *)(bufV + sub * VSZ);
    Vb[(c * H + wp) * KH + kh] = make_float2(o0r, o0i);
    Vb[(c * H + wp + 1) * KH + kh] = make_float2(o1r, o1i);
  }
  __syncthreads();

  // ---- Pass D: C2R over h (twiddles = immediates) -> s2 (aliases bufA) ----
  for (int idx = tid; idx < NB * 8 * H * 2; idx += BLK) {
    int hP = idx & 1;
    int w = (idx >> 1) % H;
    int rc = idx / (2 * H);
    int c = rc % 8, sub = rc / 8;
    const float2 *Vb = (const float2 *)(bufV + sub * VSZ) + (c * H + w) * KH;
    float2 Cv[KH];
#pragma unroll
    for (int kh = 0; kh < KH; ++kh) Cv[kh] = Vb[kh];
    float *s2c = bufA + sub * ASZ + c * CS;
    if (hP == 0) passD_rows<H, 0, CS>(Cv, s2c, w);
    else         passD_rows<H, 1, CS>(Cv, s2c, w);
  }
  __syncthreads();

  // ---- tail: LN2 -> MLP -> conv3x3(s1)+mlp -> LN -> relu -> store ----
  for (int idx = tid; idx < NB * N; idx += BLK) {
    int sub = idx / N, n = idx % N;
    const float *s2 = bufA + sub * ASZ;
    const float *sp = s1 + sub * 8 * CS;

    float v[8];
#pragma unroll
    for (int c = 0; c < 8; ++c) v[c] = s2[c * CS + n];
    float m = 0.f;
#pragma unroll
    for (int c = 0; c < 8; ++c) m += v[c];
    m *= 0.125f;
    float var = 0.f;
#pragma unroll
    for (int c = 0; c < 8; ++c) { float d = v[c] - m; var += d * d; }
    var *= 0.125f;
    float rs = rsqrtf(var + 1e-5f);
#pragma unroll
    for (int c = 0; c < 8; ++c)
      v[c] = (v[c] - m) * rs * CP[Q + O_N2G + c] + CP[Q + O_N2B + c];

    float y[8];
#pragma unroll
    for (int o = 0; o < 8; ++o) y[o] = CP[Q + O_B2 + o];
#pragma unroll 4
    for (int j = 0; j < 32; ++j) {
      float hj = CP[Q + O_B1 + j];
#pragma unroll
      for (int c = 0; c < 8; ++c) hj += v[c] * CP[Q + O_W1 + c * 32 + j];
      float g = 0.5f * hj * (1.f + erff(hj * 0.70710678118654752f));
#pragma unroll
      for (int o = 0; o < 8; ++o) y[o] += g * CP[Q + O_W2 + j * 8 + o];
    }

    int h = n / H, w = n % H;
    float acc[8];
#pragma unroll
    for (int o = 0; o < 8; ++o) acc[o] = CP[Q + O_SCB + o] + y[o];
#pragma unroll
    for (int dh = -1; dh <= 1; ++dh) {
      int hh = h + dh;
      if (hh < 0 || hh >= H) continue;
#pragma unroll
      for (int dw = -1; dw <= 1; ++dw) {
        int ww = w + dw;
        if (ww < 0 || ww >= H) continue;
        int nn = hh * H + ww;
        int k = (dh + 1) * 3 + (dw + 1);
#pragma unroll
        for (int i = 0; i < 8; ++i) {
          float xv = sp[i * CS + nn];
#pragma unroll
          for (int o = 0; o < 8; ++o)
            acc[o] += xv * CP[Q + O_SCW + (o * 8 + i) * 9 + k];
        }
      }
    }

    float mo = 0.f;
#pragma unroll
    for (int o = 0; o < 8; ++o) mo += acc[o];
    mo *= 0.125f;
    float vo = 0.f;
#pragma unroll
    for (int o = 0; o < 8; ++o) { float d = acc[o] - mo; vo += d * d; }
    vo *= 0.125f;
    float rso = rsqrtf(vo + 1e-5f);
    float rr[8];
#pragma unroll
    for (int o = 0; o < 8; ++o)
      rr[o] = fmaxf((acc[o] - mo) * rso * CP[Q + O_NOG + o] + CP[Q + O_NOB + o], 0.f);

    float *gp = out + ((size_t)(b0 + sub) * 320 + tok_off + n) * 8;
    *(float4 *)gp = make_float4(rr[0], rr[1], rr[2], rr[3]);
    *(float4 *)(gp + 4) = make_float4(rr[4], rr[5], rr[6], rr[7]);
  }
}

// Both branches in one launch: blocks [0,Bx) -> H=16 x-branch,
// [Bx, Bx+gz) -> H=8 z-branch (4 batches per block).
__global__ void __launch_bounds__(BLK, 4) sg_fused(
    const float *__restrict__ x, float *__restrict__ out, int Bx)
{
  __shared__ __align__(16) float pool[POOL_FLOATS];
  int bid = blockIdx.x;
  if (bid < Bx)
    run_branch<16, 1>(x, out, bid, 64, 0, 0, pool);
  else
    run_branch<8, 4>(x, out, bid - Bx, 0, GX_SZ, CPB, pool);
}

extern "C" void kernel_launch(void *const *d_in, const int *in_sizes, int n_in,
                              void *d_out, int out_size) {
  const float *x = (const float *)d_in[0];
  const float *n1g = (const float *)d_in[1], *n1b = (const float *)d_in[2];
  const float *n2g = (const float *)d_in[3], *n2b = (const float *)d_in[4];
  const float *n3g = (const float *)d_in[5], *n3b = (const float *)d_in[6];
  const float *c1w = (const float *)d_in[9], *c1b = (const float *)d_in[10];
  const float *n4g = (const float *)d_in[7], *n4b = (const float *)d_in[8];
  const float *c2w = (const float *)d_in[11], *c2b = (const float *)d_in[12];
  const float *m1w1 = (const float *)d_in[13], *m1b1 = (const float *)d_in[14];
  const float *m1w2 = (const float *)d_in[15], *m1b2 = (const float *)d_in[16];
  const float *m2w1 = (const float *)d_in[17], *m2b1 = (const float *)d_in[18];
  const float *m2w2 = (const float *)d_in[19], *m2b2 = (const float *)d_in[20];
  const float *cw = (const float *)d_in[21], *cwz = (const float *)d_in[22];
  float *out = (float *)d_out;
  int B = in_sizes[0] / (320 * 8);

  // Pack weights + build spectral conv kernels (cheap, weight-only).
  prep_kernel<<<1, BLK>>>(n1g, n1b, n2g, n2b, n3g, n3b, n4g, n4b,
                          c1w, c1b, c2w, c2b, m1w1, m1b1, m1w2, m1b2,
                          m2w1, m2b1, m2w2, m2b2, cw, cwz);
  void *stagep = nullptr;
  cudaGetSymbolAddress(&stagep, g_stage);
  cudaMemcpyToSymbolAsync(CP, stagep, CPN * sizeof(float), 0,
                          cudaMemcpyDeviceToDevice, 0);

  int gz = (B + 3) / 4;
  sg_fused<<<B + gz, BLK>>>(x, out, B);
}